// round 3
// baseline (speedup 1.0000x reference)
#include <cuda_runtime.h>
#include <math.h>

#define NR 1000000
#define DD 256
#define BS 4096

// ---------------- scratch (device globals: no allocations allowed) ----------
__device__ float g_s[NR];          // scores, then exp(s - max)
__device__ float g_max[BS];
__device__ float g_sum[BS];
__device__ float g_inv[BS];
__device__ float g_pooled[BS * DD];
__device__ int   g_is64;           // batch dtype flag: 1 = int64, 0 = int32

__device__ __forceinline__ int getb(const void* p, int i, int is64) {
    if (is64) return (int)((const long long*)p)[i];
    return ((const int*)p)[i];
}

// ---------------- init: zero pooled, -inf max, detect batch dtype ----------
__global__ void init_kernel(const void* batch) {
    int i = blockIdx.x * blockDim.x + threadIdx.x;
    if (i < BS * DD) g_pooled[i] = 0.f;
    if (i < BS) { g_max[i] = -INFINITY; g_sum[i] = 0.f; }
    if (i == 0) {
        // If storage is int32, reading int64 at (NR/2 - 1) merges two mid-range
        // sorted values (~2048 each) into ~2048 + 2048*2^32 >> BS. If storage is
        // int64, the value is a valid segment id < BS. Offset stays in-bounds
        // for the 4 MB int32 buffer (byte offset 3,999,992..3,999,999).
        long long v = ((const long long*)batch)[NR / 2 - 1];
        g_is64 = (v >= 0 && v < BS) ? 1 : 0;
    }
}

// ---------------- score GEMM: s = tanh(x@W1 + b1) @ w2 + b2 ----------------
// BM=64 rows/block, BN=256 (full width), BK=32. 256 threads, 4x16 microtile.
__global__ __launch_bounds__(256, 2)
void score_kernel(const float* __restrict__ x, const float* __restrict__ W1,
                  const float* __restrict__ b1, const float* __restrict__ w2,
                  const float* __restrict__ b2p) {
    __shared__ float As[64][36];     // [m][k], padded stride 36 (16B aligned)
    __shared__ float Bs[32][256];    // [k][j]
    __shared__ float red[64][16];

    const int tid = threadIdx.x;
    const int tx = tid & 15;         // 16 col-groups of 16 cols
    const int ty = tid >> 4;         // 16 row-groups of 4 rows
    const int bm = blockIdx.x * 64;

    float acc[4][16];
#pragma unroll
    for (int i = 0; i < 4; i++)
#pragma unroll
        for (int j = 0; j < 16; j++) acc[i][j] = 0.f;

    for (int kt = 0; kt < DD; kt += 32) {
        __syncthreads();
        // load A tile: 64 rows x 32 k  (2 float4 per thread, coalesced)
#pragma unroll
        for (int r = 0; r < 2; r++) {
            int idx = tid + r * 256;             // 0..511
            int m = idx >> 3, kq = idx & 7;
            float4 v = *(const float4*)(x + (size_t)(bm + m) * DD + kt + kq * 4);
            *(float4*)&As[m][kq * 4] = v;
        }
        // load B tile: 32 k x 256 j   (8 float4 per thread, coalesced)
#pragma unroll
        for (int r = 0; r < 8; r++) {
            int idx = tid + r * 256;             // 0..2047
            int k = idx >> 6, j4 = idx & 63;
            *(float4*)&Bs[k][j4 * 4] =
                *(const float4*)(W1 + (size_t)(kt + k) * DD + j4 * 4);
        }
        __syncthreads();
#pragma unroll
        for (int k = 0; k < 32; k++) {
            float a[4], b[16];
#pragma unroll
            for (int i = 0; i < 4; i++) a[i] = As[ty * 4 + i][k];
#pragma unroll
            for (int j4 = 0; j4 < 4; j4++)
                *(float4*)&b[j4 * 4] = *(float4*)&Bs[k][tx * 16 + j4 * 4];
#pragma unroll
            for (int i = 0; i < 4; i++)
#pragma unroll
                for (int j = 0; j < 16; j++) acc[i][j] += a[i] * b[j];
        }
    }

    // epilogue: per-row  sum_j w2[j] * tanh(h + b1[j]),  reduce across tx
    const float b2v = __ldg(b2p);
#pragma unroll
    for (int i = 0; i < 4; i++) {
        float t = 0.f;
#pragma unroll
        for (int j = 0; j < 16; j++) {
            int col = tx * 16 + j;
            t += __ldg(w2 + col) * tanhf(acc[i][j] + __ldg(b1 + col));
        }
        red[ty * 4 + i][tx] = t;
    }
    __syncthreads();
    if (tid < 64) {
        float t = 0.f;
#pragma unroll
        for (int q = 0; q < 16; q++) t += red[tid][q];
        g_s[bm + tid] = t + b2v;
    }
}

// ---------------- segment max (atomic float-max trick) ---------------------
__global__ void segmax_kernel(const void* batch) {
    int i = blockIdx.x * blockDim.x + threadIdx.x;
    if (i >= NR) return;
    int b = getb(batch, i, g_is64);
    float v = g_s[i];
    if (v >= 0.f) atomicMax((int*)&g_max[b], __float_as_int(v));
    else          atomicMin((unsigned int*)&g_max[b], __float_as_uint(v));
}

// ---------------- exp + segment sum ----------------------------------------
__global__ void expsum_kernel(const void* batch) {
    int i = blockIdx.x * blockDim.x + threadIdx.x;
    if (i >= NR) return;
    int b = getb(batch, i, g_is64);
    float e = expf(g_s[i] - g_max[b]);
    g_s[i] = e;
    atomicAdd(&g_sum[b], e);
}

__global__ void recip_kernel() {
    int i = blockIdx.x * blockDim.x + threadIdx.x;
    if (i < BS) g_inv[i] = 1.f / g_sum[i];
}

// ---------------- weighted pooling: exploits sorted batch ------------------
// Each block walks RPB contiguous rows; thread t owns column t. Flush to
// global only on segment boundaries -> ~2 atomicAdd rounds per segment.
#define RPB 256
__global__ void pool_kernel(const float* __restrict__ x, const void* batch) {
    int start = blockIdx.x * RPB;
    int end = min(start + RPB, NR);
    if (start >= NR) return;
    const int col = threadIdx.x;
    const int is64 = g_is64;
    float acc = 0.f;
    int cur = getb(batch, start, is64);
    for (int r = start; r < end; r++) {
        int b = getb(batch, r, is64);
        if (b != cur) {
            atomicAdd(&g_pooled[(size_t)cur * DD + col], acc);
            acc = 0.f;
            cur = b;
        }
        float alpha = g_s[r] * g_inv[b];
        acc += alpha * x[(size_t)r * DD + col];
    }
    atomicAdd(&g_pooled[(size_t)cur * DD + col], acc);
}

// ---------------- output GEMM: out = pooled @ Wp + bp ----------------------
__global__ void out_kernel(const float* __restrict__ Wp,
                           const float* __restrict__ bp,
                           float* __restrict__ out) {
    __shared__ float Ps[16][256];
    const int row0 = blockIdx.x * 16;
    const int tid = threadIdx.x;
    for (int idx = tid; idx < 16 * 256; idx += 256)
        (&Ps[0][0])[idx] = g_pooled[(size_t)row0 * DD + idx];
    __syncthreads();
    float acc[16];
#pragma unroll
    for (int r = 0; r < 16; r++) acc[r] = 0.f;
    const int col = tid;
    for (int k = 0; k < 256; k++) {
        float w = Wp[(size_t)k * DD + col];
#pragma unroll
        for (int r = 0; r < 16; r++) acc[r] += Ps[r][k] * w;
    }
    const float bb = bp[col];
#pragma unroll
    for (int r = 0; r < 16; r++)
        out[(size_t)(row0 + r) * DD + col] = acc[r] + bb;
}

// ---------------- launch ----------------------------------------------------
extern "C" void kernel_launch(void* const* d_in, const int* in_sizes, int n_in,
                              void* d_out, int out_size) {
    const float* x  = (const float*)d_in[0];
    const void*  bt = d_in[1];
    const float* W1 = (const float*)d_in[2];
    const float* b1 = (const float*)d_in[3];
    const float* w2 = (const float*)d_in[4];
    const float* b2 = (const float*)d_in[5];
    const float* Wp = (const float*)d_in[6];
    const float* bp = (const float*)d_in[7];
    float* out = (float*)d_out;

    init_kernel<<<(BS * DD + 255) / 256, 256>>>(bt);
    score_kernel<<<NR / 64, 256>>>(x, W1, b1, w2, b2);
    segmax_kernel<<<(NR + 255) / 256, 256>>>(bt);
    expsum_kernel<<<(NR + 255) / 256, 256>>>(bt);
    recip_kernel<<<(BS + 255) / 256, 256>>>();
    pool_kernel<<<(NR + RPB - 1) / RPB, 256>>>(x, bt);
    out_kernel<<<BS / 16, 256>>>(Wp, bp, out);
}

// round 5
// speedup vs baseline: 3.0458x; 3.0458x over previous
#include <cuda_runtime.h>
#include <cuda_bf16.h>
#include <math.h>
#include <stdint.h>

#define NR 1000000
#define DD 256
#define BS 4096

// ---------------- scratch (device globals: no allocations allowed) ----------
__device__ float g_s[NR];          // scores, then exp(s - max)
__device__ float g_max[BS];
__device__ float g_sum[BS];
__device__ float g_inv[BS];
__device__ float g_pooled[BS * DD];
__device__ int   g_is64;           // batch dtype flag: 1 = int64, 0 = int32
// W1 split into bf16 hi/lo, transposed to [n][k] (K contiguous per output col)
__device__ __align__(16) __nv_bfloat16 g_Bhi[DD * DD];
__device__ __align__(16) __nv_bfloat16 g_Blo[DD * DD];

__device__ __forceinline__ int getb(const void* p, int i, int is64) {
    if (is64) return (int)((const long long*)p)[i];
    return ((const int*)p)[i];
}

__device__ __forceinline__ uint32_t smem_u32(const void* p) {
    uint32_t a;
    asm("{ .reg .u64 t; cvta.to.shared.u64 t, %1; cvt.u32.u64 %0, t; }"
        : "=r"(a) : "l"(p));
    return a;
}
__device__ __forceinline__ void ldm_x4(uint32_t* r, uint32_t addr) {
    asm volatile("ldmatrix.sync.aligned.m8n8.x4.shared.b16 {%0,%1,%2,%3}, [%4];"
        : "=r"(r[0]), "=r"(r[1]), "=r"(r[2]), "=r"(r[3]) : "r"(addr));
}
__device__ __forceinline__ void mma_bf16(float* d, const uint32_t* a,
                                         const uint32_t* b) {
    asm volatile(
        "mma.sync.aligned.m16n8k16.row.col.f32.bf16.bf16.f32 "
        "{%0,%1,%2,%3}, {%4,%5,%6,%7}, {%8,%9}, {%0,%1,%2,%3};"
        : "+f"(d[0]), "+f"(d[1]), "+f"(d[2]), "+f"(d[3])
        : "r"(a[0]), "r"(a[1]), "r"(a[2]), "r"(a[3]), "r"(b[0]), "r"(b[1]));
}
__device__ __forceinline__ float tanh_fast(float v) {
    // tanh(v) = 1 - 2/(exp(2v)+1); overflow-safe
    float e = __expf(2.f * v);
    return 1.f - __fdividef(2.f, e + 1.f);
}

// ---------------- init ------------------------------------------------------
__global__ void init_kernel(const void* batch) {
    int i = blockIdx.x * blockDim.x + threadIdx.x;
    if (i < BS * DD) g_pooled[i] = 0.f;
    if (i < BS) { g_max[i] = -INFINITY; g_sum[i] = 0.f; }
    if (i == 0) {
        long long v = ((const long long*)batch)[NR / 2 - 1];
        g_is64 = (v >= 0 && v < BS) ? 1 : 0;
    }
}

// ---------------- prep: split W1 -> bf16 hi/lo, transpose to [n][k] ---------
__global__ void prep_w1_kernel(const float* __restrict__ W1) {
    int i = blockIdx.x * blockDim.x + threadIdx.x;   // 0..65535
    if (i >= DD * DD) return;
    int k = i >> 8, n = i & 255;                     // W1[k][n]
    float v = W1[i];
    __nv_bfloat16 h = __float2bfloat16(v);
    __nv_bfloat16 l = __float2bfloat16(v - __bfloat162float(h));
    g_Bhi[n * DD + k] = h;
    g_Blo[n * DD + k] = l;
}

// ---------------- score GEMM via mma.sync bf16-split ------------------------
// CTA: 512 threads = 16 warps (4 M x 4 N). Tile M=128, N=256, K chunks of 64.
// smem rows padded to 144 B for conflict-free ldmatrix.
#define APITCH 144
#define OF_AH 0
#define OF_AL 18432
#define OF_BH 36864
#define OF_BL 73728
#define SC_SMEM 110592
__global__ __launch_bounds__(512, 1)
void score_mma_kernel(const float* __restrict__ x, const float* __restrict__ b1,
                      const float* __restrict__ w2, const float* __restrict__ b2p) {
    extern __shared__ char smem[];
    const uint32_t sb = smem_u32(smem);
    const int tid = threadIdx.x;
    const int wid = tid >> 5, lane = tid & 31;
    const int mw = wid & 3;          // M warp: rows mw*32 .. +31
    const int nw = wid >> 2;         // N warp: cols nw*64 .. +63
    const int bm = blockIdx.x * 128;

    float acc[2][8][4];
#pragma unroll
    for (int a = 0; a < 2; a++)
#pragma unroll
        for (int b = 0; b < 8; b++)
#pragma unroll
            for (int c = 0; c < 4; c++) acc[a][b][c] = 0.f;

    // per-thread ldmatrix row components (lane-invariant parts)
    const int a_row_in = (lane & 15);            // + mt*16 + mw*32
    const int a_k_in   = (lane & 16) >> 1;       // 0 or 8
    const int b_n_in   = (lane & 7) + ((lane & 16) >> 1);  // + p*16 + nw*64
    const int b_k_in   = (lane & 8);             // 0 or 8

    for (int c = 0; c < 4; c++) {                // K chunks of 64
        __syncthreads();
        // ---- load A chunk: 128 rows x 64 floats -> bf16 hi/lo in smem ----
#pragma unroll
        for (int t = 0; t < 4; t++) {
            int idx = tid + t * 512;             // 0..2047 float4s
            int r = idx >> 4, q = idx & 15;
            int grow = bm + r;
            float4 v = (grow < NR)
                ? *(const float4*)(x + (size_t)grow * DD + c * 64 + q * 4)
                : make_float4(0.f, 0.f, 0.f, 0.f);
            float vv[4] = {v.x, v.y, v.z, v.w};
            unsigned short hs[4], ls[4];
#pragma unroll
            for (int j = 0; j < 4; j++) {
                __nv_bfloat16 h = __float2bfloat16(vv[j]);
                __nv_bfloat16 l = __float2bfloat16(vv[j] - __bfloat162float(h));
                hs[j] = __bfloat16_as_ushort(h);
                ls[j] = __bfloat16_as_ushort(l);
            }
            uint2 hp = make_uint2((uint32_t)hs[0] | ((uint32_t)hs[1] << 16),
                                  (uint32_t)hs[2] | ((uint32_t)hs[3] << 16));
            uint2 lp = make_uint2((uint32_t)ls[0] | ((uint32_t)ls[1] << 16),
                                  (uint32_t)ls[2] | ((uint32_t)ls[3] << 16));
            uint32_t off = (uint32_t)r * APITCH + (uint32_t)q * 8;
            *(uint2*)(smem + OF_AH + off) = hp;
            *(uint2*)(smem + OF_AL + off) = lp;
        }
        // ---- load B chunk: 256 n-rows x 64 k (hi & lo), 16B copies ------
#pragma unroll
        for (int t = 0; t < 4; t++) {
            int idx = tid + t * 512;             // 0..2047
            int n = idx >> 3, q = idx & 7;
            size_t gsrc = (size_t)n * DD + c * 64 + q * 8;
            uint32_t doff = (uint32_t)n * APITCH + (uint32_t)q * 16;
            *(uint4*)(smem + OF_BH + doff) = *(const uint4*)(g_Bhi + gsrc);
            *(uint4*)(smem + OF_BL + doff) = *(const uint4*)(g_Blo + gsrc);
        }
        __syncthreads();

        // ---- compute: 4 k16 steps ----
#pragma unroll
        for (int ks = 0; ks < 4; ks++) {
            const int k0 = ks * 16;
            uint32_t ah[2][4], al[2][4];
#pragma unroll
            for (int mt = 0; mt < 2; mt++) {
                uint32_t row = (uint32_t)(mw * 32 + mt * 16 + a_row_in);
                uint32_t col = (uint32_t)(k0 + a_k_in);
                uint32_t off = row * APITCH + col * 2;
                ldm_x4(ah[mt], sb + OF_AH + off);
                ldm_x4(al[mt], sb + OF_AL + off);
            }
#pragma unroll
            for (int p = 0; p < 4; p++) {        // n-tile pairs
                uint32_t nrow = (uint32_t)(nw * 64 + p * 16 + b_n_in);
                uint32_t col = (uint32_t)(k0 + b_k_in);
                uint32_t off = nrow * APITCH + col * 2;
                uint32_t bh[4], bl[4];
                ldm_x4(bh, sb + OF_BH + off);
                ldm_x4(bl, sb + OF_BL + off);
#pragma unroll
                for (int mt = 0; mt < 2; mt++) {
#pragma unroll
                    for (int half = 0; half < 2; half++) {
                        int nt = p * 2 + half;
                        float* d = acc[mt][nt];
                        mma_bf16(d, ah[mt], bh + half * 2);   // hi*hi
                        mma_bf16(d, ah[mt], bl + half * 2);   // hi*lo
                        mma_bf16(d, al[mt], bh + half * 2);   // lo*hi
                    }
                }
            }
        }
    }

    // ---- epilogue: s = sum_n w2[n]*tanh(h + b1[n]) + b2 ----
    // D frag: d0,d1 -> (row = lane/4, col = (lane&3)*2+{0,1}); d2,d3 -> row+8
    float part[2][2] = {{0.f, 0.f}, {0.f, 0.f}};   // [mt][rowhalf]
#pragma unroll
    for (int mt = 0; mt < 2; mt++) {
#pragma unroll
        for (int nt = 0; nt < 8; nt++) {
            int col0 = nw * 64 + nt * 8 + (lane & 3) * 2;
            float w0 = __ldg(w2 + col0), w1v = __ldg(w2 + col0 + 1);
            float c0 = __ldg(b1 + col0), c1 = __ldg(b1 + col0 + 1);
            const float* d = acc[mt][nt];
            part[mt][0] += w0 * tanh_fast(d[0] + c0) + w1v * tanh_fast(d[1] + c1);
            part[mt][1] += w0 * tanh_fast(d[2] + c0) + w1v * tanh_fast(d[3] + c1);
        }
    }
    // reduce across the 4 lanes sharing each row
#pragma unroll
    for (int mt = 0; mt < 2; mt++)
#pragma unroll
        for (int h = 0; h < 2; h++) {
            part[mt][h] += __shfl_xor_sync(0xFFFFFFFF, part[mt][h], 1);
            part[mt][h] += __shfl_xor_sync(0xFFFFFFFF, part[mt][h], 2);
        }
    __syncthreads();                              // smem reuse (overlays A_hi)
    float* red = (float*)smem;                    // [128][4]
    if ((lane & 3) == 0) {
#pragma unroll
        for (int mt = 0; mt < 2; mt++)
#pragma unroll
            for (int h = 0; h < 2; h++) {
                int rowl = mw * 32 + mt * 16 + h * 8 + (lane >> 2);
                red[rowl * 4 + nw] = part[mt][h];
            }
    }
    __syncthreads();
    if (tid < 128) {
        int grow = bm + tid;
        if (grow < NR) {
            float v = red[tid * 4] + red[tid * 4 + 1] + red[tid * 4 + 2] +
                      red[tid * 4 + 3];
            g_s[grow] = v + __ldg(b2p);
        }
    }
}

// ---------------- segment max (atomic float-max trick) ---------------------
__global__ void segmax_kernel(const void* batch) {
    int i = blockIdx.x * blockDim.x + threadIdx.x;
    if (i >= NR) return;
    int b = getb(batch, i, g_is64);
    float v = g_s[i];
    if (v >= 0.f) atomicMax((int*)&g_max[b], __float_as_int(v));
    else          atomicMin((unsigned int*)&g_max[b], __float_as_uint(v));
}

// ---------------- exp + segment sum ----------------------------------------
__global__ void expsum_kernel(const void* batch) {
    int i = blockIdx.x * blockDim.x + threadIdx.x;
    if (i >= NR) return;
    int b = getb(batch, i, g_is64);
    float e = expf(g_s[i] - g_max[b]);
    g_s[i] = e;
    atomicAdd(&g_sum[b], e);
}

__global__ void recip_kernel() {
    int i = blockIdx.x * blockDim.x + threadIdx.x;
    if (i < BS) g_inv[i] = 1.f / g_sum[i];
}

// ---------------- weighted pooling: exploits sorted batch ------------------
#define RPB 256
__global__ void pool_kernel(const float* __restrict__ x, const void* batch) {
    int start = blockIdx.x * RPB;
    int end = min(start + RPB, NR);
    if (start >= NR) return;
    const int col = threadIdx.x;
    const int is64 = g_is64;
    float acc = 0.f;
    int cur = getb(batch, start, is64);
    for (int r = start; r < end; r++) {
        int b = getb(batch, r, is64);
        if (b != cur) {
            atomicAdd(&g_pooled[(size_t)cur * DD + col], acc);
            acc = 0.f;
            cur = b;
        }
        float alpha = g_s[r] * g_inv[b];
        acc += alpha * x[(size_t)r * DD + col];
    }
    atomicAdd(&g_pooled[(size_t)cur * DD + col], acc);
}

// ---------------- output GEMM: out = pooled @ Wp + bp ----------------------
__global__ void out_kernel(const float* __restrict__ Wp,
                           const float* __restrict__ bp,
                           float* __restrict__ out) {
    __shared__ float Ps[16][256];
    const int row0 = blockIdx.x * 16;
    const int tid = threadIdx.x;
    for (int idx = tid; idx < 16 * 256; idx += 256)
        (&Ps[0][0])[idx] = g_pooled[(size_t)row0 * DD + idx];
    __syncthreads();
    float acc[16];
#pragma unroll
    for (int r = 0; r < 16; r++) acc[r] = 0.f;
    const int col = tid;
    for (int k = 0; k < 256; k++) {
        float w = Wp[(size_t)k * DD + col];
#pragma unroll
        for (int r = 0; r < 16; r++) acc[r] += Ps[r][k] * w;
    }
    const float bb = bp[col];
#pragma unroll
    for (int r = 0; r < 16; r++)
        out[(size_t)(row0 + r) * DD + col] = acc[r] + bb;
}

// ---------------- launch ----------------------------------------------------
extern "C" void kernel_launch(void* const* d_in, const int* in_sizes, int n_in,
                              void* d_out, int out_size) {
    const float* x  = (const float*)d_in[0];
    const void*  bt = d_in[1];
    const float* W1 = (const float*)d_in[2];
    const float* b1 = (const float*)d_in[3];
    const float* w2 = (const float*)d_in[4];
    const float* b2 = (const float*)d_in[5];
    const float* Wp = (const float*)d_in[6];
    const float* bp = (const float*)d_in[7];
    float* out = (float*)d_out;

    cudaFuncSetAttribute(score_mma_kernel,
                         cudaFuncAttributeMaxDynamicSharedMemorySize, SC_SMEM);

    init_kernel<<<(BS * DD + 255) / 256, 256>>>(bt);
    prep_w1_kernel<<<(DD * DD + 255) / 256, 256>>>(W1);
    score_mma_kernel<<<(NR + 127) / 128, 512, SC_SMEM>>>(x, b1, w2, b2);
    segmax_kernel<<<(NR + 255) / 256, 256>>>(bt);
    expsum_kernel<<<(NR + 255) / 256, 256>>>(bt);
    recip_kernel<<<(BS + 255) / 256, 256>>>();
    pool_kernel<<<(NR + RPB - 1) / RPB, 256>>>(x, bt);
    out_kernel<<<BS / 16, 256>>>(Wp, bp, out);
}

// round 7
// speedup vs baseline: 4.6007x; 1.5105x over previous
#include <cuda_runtime.h>
#include <cuda_bf16.h>
#include <math.h>
#include <stdint.h>

#define NR 1000000
#define DD 256
#define BS 4096

// ---------------- scratch (device globals: no allocations allowed) ----------
__device__ float g_s[NR];          // scores, then exp(s - max)
__device__ float g_max[BS];
__device__ float g_sum[BS];
__device__ float g_inv[BS];
__device__ float g_pooled[BS * DD];
__device__ int   g_is64;           // batch dtype flag: 1 = int64, 0 = int32
// W1 split into bf16 hi/lo, transposed to [n][k] (K contiguous per output col)
__device__ __align__(16) __nv_bfloat16 g_Bhi[DD * DD];
__device__ __align__(16) __nv_bfloat16 g_Blo[DD * DD];

__device__ __forceinline__ int getb(const void* p, int i, int is64) {
    if (is64) return (int)((const long long*)p)[i];
    return ((const int*)p)[i];
}

__device__ __forceinline__ uint32_t smem_u32(const void* p) {
    uint32_t a;
    asm("{ .reg .u64 t; cvta.to.shared.u64 t, %1; cvt.u32.u64 %0, t; }"
        : "=r"(a) : "l"(p));
    return a;
}
__device__ __forceinline__ void ldm_x4(uint32_t* r, uint32_t addr) {
    asm volatile("ldmatrix.sync.aligned.m8n8.x4.shared.b16 {%0,%1,%2,%3}, [%4];"
        : "=r"(r[0]), "=r"(r[1]), "=r"(r[2]), "=r"(r[3]) : "r"(addr));
}
__device__ __forceinline__ void mma_bf16(float* d, const uint32_t* a,
                                         const uint32_t* b) {
    asm volatile(
        "mma.sync.aligned.m16n8k16.row.col.f32.bf16.bf16.f32 "
        "{%0,%1,%2,%3}, {%4,%5,%6,%7}, {%8,%9}, {%0,%1,%2,%3};"
        : "+f"(d[0]), "+f"(d[1]), "+f"(d[2]), "+f"(d[3])
        : "r"(a[0]), "r"(a[1]), "r"(a[2]), "r"(a[3]), "r"(b[0]), "r"(b[1]));
}
__device__ __forceinline__ void cpasync16(uint32_t dst, const void* src) {
    asm volatile("cp.async.cg.shared.global [%0], [%1], 16;"
                 :: "r"(dst), "l"(src) : "memory");
}
#define CP_COMMIT() asm volatile("cp.async.commit_group;" ::: "memory")
#define CP_WAIT0()  asm volatile("cp.async.wait_group 0;" ::: "memory")

__device__ __forceinline__ float tanh_fast(float v) {
    float e = __expf(2.f * v);
    return 1.f - __fdividef(2.f, e + 1.f);
}

// ---------------- init ------------------------------------------------------
__global__ void init_kernel(const void* batch) {
    int i = blockIdx.x * blockDim.x + threadIdx.x;
    if (i < BS * DD) g_pooled[i] = 0.f;
    if (i < BS) { g_max[i] = -INFINITY; g_sum[i] = 0.f; }
    if (i == 0) {
        long long v = ((const long long*)batch)[NR / 2 - 1];
        g_is64 = (v >= 0 && v < BS) ? 1 : 0;
    }
}

// ---------------- prep: split W1 -> bf16 hi/lo, transpose to [n][k] ---------
__global__ void prep_w1_kernel(const float* __restrict__ W1) {
    int i = blockIdx.x * blockDim.x + threadIdx.x;
    if (i >= DD * DD) return;
    int k = i >> 8, n = i & 255;                     // W1[k][n]
    float v = W1[i];
    __nv_bfloat16 h = __float2bfloat16(v);
    __nv_bfloat16 l = __float2bfloat16(v - __bfloat162float(h));
    g_Bhi[n * DD + k] = h;
    g_Blo[n * DD + k] = l;
}

// ---------------- score GEMM via mma.sync bf16-split, double-buffered -------
// CTA: 512 threads = 16 warps (4 M x 4 N). Tile M=128, N=256, K chunks of 64.
#define APITCH 144
#define BUFSZ  110592
#define OF_AH  0
#define OF_AL  18432
#define OF_BH  36864
#define OF_BL  73728
#define SC_SMEM (2 * BUFSZ)
__global__ __launch_bounds__(512, 1)
void score_mma_kernel(const float* __restrict__ x, const float* __restrict__ b1,
                      const float* __restrict__ w2, const float* __restrict__ b2p) {
    extern __shared__ char smem[];
    const uint32_t sb = smem_u32(smem);
    const int tid = threadIdx.x;
    const int wid = tid >> 5, lane = tid & 31;
    const int mw = wid & 3;          // M warp: rows mw*32 .. +31
    const int nw = wid >> 2;         // N warp: cols nw*64 .. +63
    const int bm = blockIdx.x * 128;

    float acc[2][8][4];
#pragma unroll
    for (int a = 0; a < 2; a++)
#pragma unroll
        for (int b = 0; b < 8; b++)
#pragma unroll
            for (int c = 0; c < 4; c++) acc[a][b][c] = 0.f;

    const int a_row_in = (lane & 15);
    const int a_k_in   = (lane & 16) >> 1;
    const int b_n_in   = (lane & 7) + ((lane & 16) >> 1);
    const int b_k_in   = (lane & 8);

    auto loadB = [&](int c, int buf) {
        uint32_t base = sb + buf * BUFSZ;
#pragma unroll
        for (int t = 0; t < 4; t++) {
            int idx = tid + t * 512;             // 0..2047
            int n = idx >> 3, q = idx & 7;
            uint32_t doff = (uint32_t)n * APITCH + (uint32_t)q * 16;
            size_t gsrc = (size_t)n * DD + c * 64 + q * 8;
            cpasync16(base + OF_BH + doff, g_Bhi + gsrc);
            cpasync16(base + OF_BL + doff, g_Blo + gsrc);
        }
        CP_COMMIT();
    };
    auto loadA = [&](int c, float4* st) {
#pragma unroll
        for (int t = 0; t < 4; t++) {
            int idx = tid + t * 512;             // 0..2047 float4s
            int r = idx >> 4, q = idx & 15;
            int grow = bm + r;
            st[t] = (grow < NR)
                ? *(const float4*)(x + (size_t)grow * DD + c * 64 + q * 4)
                : make_float4(0.f, 0.f, 0.f, 0.f);
        }
    };
    auto storeA = [&](const float4* st, int buf) {
        char* base = smem + buf * BUFSZ;
#pragma unroll
        for (int t = 0; t < 4; t++) {
            int idx = tid + t * 512;
            int r = idx >> 4, q = idx & 15;
            float vv[4] = {st[t].x, st[t].y, st[t].z, st[t].w};
            unsigned short hs[4], ls[4];
#pragma unroll
            for (int j = 0; j < 4; j++) {
                __nv_bfloat16 h = __float2bfloat16(vv[j]);
                __nv_bfloat16 l = __float2bfloat16(vv[j] - __bfloat162float(h));
                hs[j] = __bfloat16_as_ushort(h);
                ls[j] = __bfloat16_as_ushort(l);
            }
            uint2 hp = make_uint2((uint32_t)hs[0] | ((uint32_t)hs[1] << 16),
                                  (uint32_t)hs[2] | ((uint32_t)hs[3] << 16));
            uint2 lp = make_uint2((uint32_t)ls[0] | ((uint32_t)ls[1] << 16),
                                  (uint32_t)ls[2] | ((uint32_t)ls[3] << 16));
            uint32_t off = (uint32_t)r * APITCH + (uint32_t)q * 8;
            *(uint2*)(base + OF_AH + off) = hp;
            *(uint2*)(base + OF_AL + off) = lp;
        }
    };

    // ---- prologue: fill buffer 0 ----
    float4 st[4];
    loadB(0, 0);
    loadA(0, st);
    storeA(st, 0);
    CP_WAIT0();
    __syncthreads();

#pragma unroll 1
    for (int c = 0; c < 4; c++) {
        const int cur = c & 1, nxt = cur ^ 1;
        if (c < 3) {
            loadB(c + 1, nxt);       // cp.async overlaps MMA burst
            loadA(c + 1, st);        // LDG latency hidden under MMA burst
        }
        // ---- compute on buf[cur]: 4 k16 steps ----
        const uint32_t abase = sb + (uint32_t)cur * BUFSZ;
#pragma unroll
        for (int ks = 0; ks < 4; ks++) {
            const int k0 = ks * 16;
            uint32_t ah[2][4], al[2][4];
#pragma unroll
            for (int mt = 0; mt < 2; mt++) {
                uint32_t row = (uint32_t)(mw * 32 + mt * 16 + a_row_in);
                uint32_t col = (uint32_t)(k0 + a_k_in);
                uint32_t off = row * APITCH + col * 2;
                ldm_x4(ah[mt], abase + OF_AH + off);
                ldm_x4(al[mt], abase + OF_AL + off);
            }
#pragma unroll
            for (int p = 0; p < 4; p++) {
                uint32_t nrow = (uint32_t)(nw * 64 + p * 16 + b_n_in);
                uint32_t col = (uint32_t)(k0 + b_k_in);
                uint32_t off = nrow * APITCH + col * 2;
                uint32_t bh[4], bl[4];
                ldm_x4(bh, abase + OF_BH + off);
                ldm_x4(bl, abase + OF_BL + off);
#pragma unroll
                for (int mt = 0; mt < 2; mt++) {
#pragma unroll
                    for (int half = 0; half < 2; half++) {
                        int nt = p * 2 + half;
                        float* d = acc[mt][nt];
                        mma_bf16(d, ah[mt], bh + half * 2);   // hi*hi
                        mma_bf16(d, ah[mt], bl + half * 2);   // hi*lo
                        mma_bf16(d, al[mt], bh + half * 2);   // lo*hi
                    }
                }
            }
        }
        if (c < 3) {
            storeA(st, nxt);         // short convert tail
            CP_WAIT0();              // B(c+1) landed
        }
        __syncthreads();
    }

    // ---- epilogue: s = sum_n w2[n]*tanh(h + b1[n]) + b2 ----
    float part[2][2] = {{0.f, 0.f}, {0.f, 0.f}};
#pragma unroll
    for (int mt = 0; mt < 2; mt++) {
#pragma unroll
        for (int nt = 0; nt < 8; nt++) {
            int col0 = nw * 64 + nt * 8 + (lane & 3) * 2;
            float w0 = __ldg(w2 + col0), w1v = __ldg(w2 + col0 + 1);
            float c0 = __ldg(b1 + col0), c1 = __ldg(b1 + col0 + 1);
            const float* d = acc[mt][nt];
            part[mt][0] += w0 * tanh_fast(d[0] + c0) + w1v * tanh_fast(d[1] + c1);
            part[mt][1] += w0 * tanh_fast(d[2] + c0) + w1v * tanh_fast(d[3] + c1);
        }
    }
#pragma unroll
    for (int mt = 0; mt < 2; mt++)
#pragma unroll
        for (int h = 0; h < 2; h++) {
            part[mt][h] += __shfl_xor_sync(0xFFFFFFFF, part[mt][h], 1);
            part[mt][h] += __shfl_xor_sync(0xFFFFFFFF, part[mt][h], 2);
        }
    __syncthreads();
    float* red = (float*)smem;                    // [128][4]
    if ((lane & 3) == 0) {
#pragma unroll
        for (int mt = 0; mt < 2; mt++)
#pragma unroll
            for (int h = 0; h < 2; h++) {
                int rowl = mw * 32 + mt * 16 + h * 8 + (lane >> 2);
                red[rowl * 4 + nw] = part[mt][h];
            }
    }
    __syncthreads();
    if (tid < 128) {
        int grow = bm + tid;
        if (grow < NR) {
            float v = red[tid * 4] + red[tid * 4 + 1] + red[tid * 4 + 2] +
                      red[tid * 4 + 3];
            g_s[grow] = v + __ldg(b2p);
        }
    }
}

// ---------------- segment max (warp-aggregated atomics) --------------------
__device__ __forceinline__ void atomic_fmax(float* addr, float v) {
    if (v >= 0.f) atomicMax((int*)addr, __float_as_int(v));
    else          atomicMin((unsigned int*)addr, __float_as_uint(v));
}
__global__ void segmax_kernel(const void* batch) {
    int i = blockIdx.x * blockDim.x + threadIdx.x;
    unsigned m = __ballot_sync(0xFFFFFFFF, i < NR);
    if (i >= NR) return;
    int b = getb(batch, i, g_is64);
    float v = g_s[i];
    int b0 = __shfl_sync(m, b, 0);
    if (m == 0xFFFFFFFFu && __all_sync(m, b == b0)) {
#pragma unroll
        for (int o = 16; o; o >>= 1)
            v = fmaxf(v, __shfl_xor_sync(0xFFFFFFFFu, v, o));
        if ((threadIdx.x & 31) == 0) atomic_fmax(&g_max[b], v);
    } else {
        atomic_fmax(&g_max[b], v);
    }
}

// ---------------- exp + segment sum (warp-aggregated) ----------------------
__global__ void expsum_kernel(const void* batch) {
    int i = blockIdx.x * blockDim.x + threadIdx.x;
    unsigned m = __ballot_sync(0xFFFFFFFF, i < NR);
    if (i >= NR) return;
    int b = getb(batch, i, g_is64);
    float e = expf(g_s[i] - g_max[b]);
    g_s[i] = e;
    int b0 = __shfl_sync(m, b, 0);
    if (m == 0xFFFFFFFFu && __all_sync(m, b == b0)) {
        float s = e;
#pragma unroll
        for (int o = 16; o; o >>= 1)
            s += __shfl_xor_sync(0xFFFFFFFFu, s, o);
        if ((threadIdx.x & 31) == 0) atomicAdd(&g_sum[b], s);
    } else {
        atomicAdd(&g_sum[b], e);
    }
}

__global__ void recip_kernel() {
    int i = blockIdx.x * blockDim.x + threadIdx.x;
    if (i < BS) g_inv[i] = 1.f / g_sum[i];
}

// ---------------- weighted pooling: exploits sorted batch ------------------
#define RPB 256
__global__ void pool_kernel(const float* __restrict__ x, const void* batch) {
    int start = blockIdx.x * RPB;
    int end = min(start + RPB, NR);
    if (start >= NR) return;
    const int col = threadIdx.x;
    const int is64 = g_is64;
    float acc = 0.f;
    int cur = getb(batch, start, is64);
    for (int r = start; r < end; r++) {
        int b = getb(batch, r, is64);
        if (b != cur) {
            atomicAdd(&g_pooled[(size_t)cur * DD + col], acc);
            acc = 0.f;
            cur = b;
        }
        float alpha = g_s[r] * g_inv[b];
        acc += alpha * x[(size_t)r * DD + col];
    }
    atomicAdd(&g_pooled[(size_t)cur * DD + col], acc);
}

// ---------------- output GEMM: out = pooled @ Wp + bp ----------------------
__global__ void out_kernel(const float* __restrict__ Wp,
                           const float* __restrict__ bp,
                           float* __restrict__ out) {
    __shared__ float Ps[16][256];
    const int row0 = blockIdx.x * 16;
    const int tid = threadIdx.x;
    for (int idx = tid; idx < 16 * 256; idx += 256)
        (&Ps[0][0])[idx] = g_pooled[(size_t)row0 * DD + idx];
    __syncthreads();
    float acc[16];
#pragma unroll
    for (int r = 0; r < 16; r++) acc[r] = 0.f;
    const int col = tid;
    for (int k = 0; k < 256; k++) {
        float w = Wp[(size_t)k * DD + col];
#pragma unroll
        for (int r = 0; r < 16; r++) acc[r] += Ps[r][k] * w;
    }
    const float bb = bp[col];
#pragma unroll
    for (int r = 0; r < 16; r++)
        out[(size_t)(row0 + r) * DD + col] = acc[r] + bb;
}

// ---------------- launch ----------------------------------------------------
extern "C" void kernel_launch(void* const* d_in, const int* in_sizes, int n_in,
                              void* d_out, int out_size) {
    const float* x  = (const float*)d_in[0];
    const void*  bt = d_in[1];
    const float* W1 = (const float*)d_in[2];
    const float* b1 = (const float*)d_in[3];
    const float* w2 = (const float*)d_in[4];
    const float* b2 = (const float*)d_in[5];
    const float* Wp = (const float*)d_in[6];
    const float* bp = (const float*)d_in[7];
    float* out = (float*)d_out;

    cudaFuncSetAttribute(score_mma_kernel,
                         cudaFuncAttributeMaxDynamicSharedMemorySize, SC_SMEM);

    init_kernel<<<(BS * DD + 255) / 256, 256>>>(bt);
    prep_w1_kernel<<<(DD * DD + 255) / 256, 256>>>(W1);
    score_mma_kernel<<<(NR + 127) / 128, 512, SC_SMEM>>>(x, b1, w2, b2);
    segmax_kernel<<<(NR + 255) / 256, 256>>>(bt);
    expsum_kernel<<<(NR + 255) / 256, 256>>>(bt);
    recip_kernel<<<(BS + 255) / 256, 256>>>();
    pool_kernel<<<(NR + RPB - 1) / RPB, 256>>>(x, bt);
    out_kernel<<<BS / 16, 256>>>(Wp, bp, out);
}

// round 8
// speedup vs baseline: 5.6049x; 1.2183x over previous
#include <cuda_runtime.h>
#include <cuda_bf16.h>
#include <cuda_fp16.h>
#include <math.h>
#include <stdint.h>

#define NR 1000000
#define DD 256
#define BS 4096

// ---------------- scratch (device globals: no allocations allowed) ----------
__device__ float g_s[NR];          // scores, then exp(s - max)
__device__ float g_max[BS];
__device__ float g_sum[BS];
__device__ float g_inv[BS];
__device__ float g_pooled[BS * DD];
__device__ int   g_is64;           // batch dtype flag: 1 = int64, 0 = int32
// W1 as fp16, transposed to [n][k] (K contiguous per output column)
__device__ __align__(16) __half g_Bh16[DD * DD];

__device__ __forceinline__ int getb(const void* p, int i, int is64) {
    if (is64) return (int)((const long long*)p)[i];
    return ((const int*)p)[i];
}

__device__ __forceinline__ uint32_t smem_u32(const void* p) {
    uint32_t a;
    asm("{ .reg .u64 t; cvta.to.shared.u64 t, %1; cvt.u32.u64 %0, t; }"
        : "=r"(a) : "l"(p));
    return a;
}
__device__ __forceinline__ void ldm_x4(uint32_t* r, uint32_t addr) {
    asm volatile("ldmatrix.sync.aligned.m8n8.x4.shared.b16 {%0,%1,%2,%3}, [%4];"
        : "=r"(r[0]), "=r"(r[1]), "=r"(r[2]), "=r"(r[3]) : "r"(addr));
}
__device__ __forceinline__ void mma_f16(float* d, const uint32_t* a,
                                        const uint32_t* b) {
    asm volatile(
        "mma.sync.aligned.m16n8k16.row.col.f32.f16.f16.f32 "
        "{%0,%1,%2,%3}, {%4,%5,%6,%7}, {%8,%9}, {%0,%1,%2,%3};"
        : "+f"(d[0]), "+f"(d[1]), "+f"(d[2]), "+f"(d[3])
        : "r"(a[0]), "r"(a[1]), "r"(a[2]), "r"(a[3]), "r"(b[0]), "r"(b[1]));
}
__device__ __forceinline__ void cpasync16(uint32_t dst, const void* src) {
    asm volatile("cp.async.cg.shared.global [%0], [%1], 16;"
                 :: "r"(dst), "l"(src) : "memory");
}
#define CP_COMMIT() asm volatile("cp.async.commit_group;" ::: "memory")
#define CP_WAIT0()  asm volatile("cp.async.wait_group 0;" ::: "memory")

__device__ __forceinline__ float tanh_fast(float v) {
    float e = __expf(2.f * v);
    return 1.f - __fdividef(2.f, e + 1.f);
}

// ---------------- init ------------------------------------------------------
__global__ void init_kernel(const void* batch) {
    int i = blockIdx.x * blockDim.x + threadIdx.x;
    if (i < BS * DD) g_pooled[i] = 0.f;
    if (i < BS) { g_max[i] = -INFINITY; g_sum[i] = 0.f; }
    if (i == 0) {
        long long v = ((const long long*)batch)[NR / 2 - 1];
        g_is64 = (v >= 0 && v < BS) ? 1 : 0;
    }
}

// ---------------- prep: W1 -> fp16, transpose to [n][k] ---------------------
__global__ void prep_w1_kernel(const float* __restrict__ W1) {
    int i = blockIdx.x * blockDim.x + threadIdx.x;
    if (i >= DD * DD) return;
    int k = i >> 8, n = i & 255;                     // W1[k][n]
    g_Bh16[n * DD + k] = __float2half_rn(W1[i]);
}

// ---------------- dummy: shifts score to 4th launch so ncu profiles it ------
__global__ void dummy_kernel() {}

// ---------------- score GEMM: fp16 2-term split (Ah*W + Al*W) ---------------
// CTA: 512 threads = 16 warps (4 M x 4 N). Tile M=128, N=256, K chunks of 64.
#define APITCH 144
#define BUFSZ  73728
#define OF_AH  0
#define OF_AL  18432
#define OF_BH  36864
#define SC_SMEM (2 * BUFSZ)
__global__ __launch_bounds__(512, 1)
void score_mma_kernel(const float* __restrict__ x, const float* __restrict__ b1,
                      const float* __restrict__ w2, const float* __restrict__ b2p) {
    extern __shared__ char smem[];
    const uint32_t sb = smem_u32(smem);
    const int tid = threadIdx.x;
    const int wid = tid >> 5, lane = tid & 31;
    const int mw = wid & 3;          // M warp: rows mw*32 .. +31
    const int nw = wid >> 2;         // N warp: cols nw*64 .. +63
    const int bm = blockIdx.x * 128;

    float acc[2][8][4];
#pragma unroll
    for (int a = 0; a < 2; a++)
#pragma unroll
        for (int b = 0; b < 8; b++)
#pragma unroll
            for (int c = 0; c < 4; c++) acc[a][b][c] = 0.f;

    const int a_row_in = (lane & 15);
    const int a_k_in   = (lane & 16) >> 1;
    const int b_n_in   = (lane & 7) + ((lane & 16) >> 1);
    const int b_k_in   = (lane & 8);

    auto loadB = [&](int c, int buf) {
        uint32_t base = sb + buf * BUFSZ;
#pragma unroll
        for (int t = 0; t < 4; t++) {
            int idx = tid + t * 512;             // 0..2047
            int n = idx >> 3, q = idx & 7;
            uint32_t doff = (uint32_t)n * APITCH + (uint32_t)q * 16;
            size_t gsrc = (size_t)n * DD + c * 64 + q * 8;
            cpasync16(base + OF_BH + doff, g_Bh16 + gsrc);
        }
        CP_COMMIT();
    };
    auto loadA = [&](int c, float4* st) {
#pragma unroll
        for (int t = 0; t < 4; t++) {
            int idx = tid + t * 512;             // 0..2047 float4s
            int r = idx >> 4, q = idx & 15;
            int grow = bm + r;
            st[t] = (grow < NR)
                ? *(const float4*)(x + (size_t)grow * DD + c * 64 + q * 4)
                : make_float4(0.f, 0.f, 0.f, 0.f);
        }
    };
    auto storeA = [&](const float4* st, int buf) {
        char* base = smem + buf * BUFSZ;
#pragma unroll
        for (int t = 0; t < 4; t++) {
            int idx = tid + t * 512;
            int r = idx >> 4, q = idx & 15;
            float vv[4] = {st[t].x, st[t].y, st[t].z, st[t].w};
            unsigned short hs[4], ls[4];
#pragma unroll
            for (int j = 0; j < 4; j++) {
                __half h = __float2half_rn(vv[j]);
                __half l = __float2half_rn(vv[j] - __half2float(h));
                hs[j] = __half_as_ushort(h);
                ls[j] = __half_as_ushort(l);
            }
            uint2 hp = make_uint2((uint32_t)hs[0] | ((uint32_t)hs[1] << 16),
                                  (uint32_t)hs[2] | ((uint32_t)hs[3] << 16));
            uint2 lp = make_uint2((uint32_t)ls[0] | ((uint32_t)ls[1] << 16),
                                  (uint32_t)ls[2] | ((uint32_t)ls[3] << 16));
            uint32_t off = (uint32_t)r * APITCH + (uint32_t)q * 8;
            *(uint2*)(base + OF_AH + off) = hp;
            *(uint2*)(base + OF_AL + off) = lp;
        }
    };

    // ---- prologue: fill buffer 0 ----
    float4 st[4];
    loadB(0, 0);
    loadA(0, st);
    storeA(st, 0);
    CP_WAIT0();
    __syncthreads();

#pragma unroll 1
    for (int c = 0; c < 4; c++) {
        const int cur = c & 1, nxt = cur ^ 1;
        if (c < 3) {
            loadB(c + 1, nxt);       // cp.async overlaps MMA burst
            loadA(c + 1, st);        // LDG latency hidden under MMA burst
        }
        // ---- compute on buf[cur]: 4 k16 steps ----
        const uint32_t abase = sb + (uint32_t)cur * BUFSZ;
#pragma unroll
        for (int ks = 0; ks < 4; ks++) {
            const int k0 = ks * 16;
            uint32_t ah[2][4], al[2][4];
#pragma unroll
            for (int mt = 0; mt < 2; mt++) {
                uint32_t row = (uint32_t)(mw * 32 + mt * 16 + a_row_in);
                uint32_t col = (uint32_t)(k0 + a_k_in);
                uint32_t off = row * APITCH + col * 2;
                ldm_x4(ah[mt], abase + OF_AH + off);
                ldm_x4(al[mt], abase + OF_AL + off);
            }
#pragma unroll
            for (int p = 0; p < 4; p++) {
                uint32_t nrow = (uint32_t)(nw * 64 + p * 16 + b_n_in);
                uint32_t col = (uint32_t)(k0 + b_k_in);
                uint32_t off = nrow * APITCH + col * 2;
                uint32_t bh[4];
                ldm_x4(bh, abase + OF_BH + off);
#pragma unroll
                for (int mt = 0; mt < 2; mt++) {
#pragma unroll
                    for (int half = 0; half < 2; half++) {
                        int nt = p * 2 + half;
                        float* d = acc[mt][nt];
                        mma_f16(d, ah[mt], bh + half * 2);    // hi * W
                        mma_f16(d, al[mt], bh + half * 2);    // lo * W
                    }
                }
            }
        }
        if (c < 3) {
            storeA(st, nxt);         // short convert tail
            CP_WAIT0();              // B(c+1) landed
        }
        __syncthreads();
    }

    // ---- epilogue: s = sum_n w2[n]*tanh(h + b1[n]) + b2 ----
    float part[2][2] = {{0.f, 0.f}, {0.f, 0.f}};
#pragma unroll
    for (int mt = 0; mt < 2; mt++) {
#pragma unroll
        for (int nt = 0; nt < 8; nt++) {
            int col0 = nw * 64 + nt * 8 + (lane & 3) * 2;
            float w0 = __ldg(w2 + col0), w1v = __ldg(w2 + col0 + 1);
            float c0 = __ldg(b1 + col0), c1 = __ldg(b1 + col0 + 1);
            const float* d = acc[mt][nt];
            part[mt][0] += w0 * tanh_fast(d[0] + c0) + w1v * tanh_fast(d[1] + c1);
            part[mt][1] += w0 * tanh_fast(d[2] + c0) + w1v * tanh_fast(d[3] + c1);
        }
    }
#pragma unroll
    for (int mt = 0; mt < 2; mt++)
#pragma unroll
        for (int h = 0; h < 2; h++) {
            part[mt][h] += __shfl_xor_sync(0xFFFFFFFF, part[mt][h], 1);
            part[mt][h] += __shfl_xor_sync(0xFFFFFFFF, part[mt][h], 2);
        }
    __syncthreads();
    float* red = (float*)smem;                    // [128][4]
    if ((lane & 3) == 0) {
#pragma unroll
        for (int mt = 0; mt < 2; mt++)
#pragma unroll
            for (int h = 0; h < 2; h++) {
                int rowl = mw * 32 + mt * 16 + h * 8 + (lane >> 2);
                red[rowl * 4 + nw] = part[mt][h];
            }
    }
    __syncthreads();
    if (tid < 128) {
        int grow = bm + tid;
        if (grow < NR) {
            float v = red[tid * 4] + red[tid * 4 + 1] + red[tid * 4 + 2] +
                      red[tid * 4 + 3];
            g_s[grow] = v + __ldg(b2p);
        }
    }
}

// ---------------- segment max (warp-aggregated atomics) --------------------
__device__ __forceinline__ void atomic_fmax(float* addr, float v) {
    if (v >= 0.f) atomicMax((int*)addr, __float_as_int(v));
    else          atomicMin((unsigned int*)addr, __float_as_uint(v));
}
__global__ void segmax_kernel(const void* batch) {
    int i = blockIdx.x * blockDim.x + threadIdx.x;
    unsigned m = __ballot_sync(0xFFFFFFFF, i < NR);
    if (i >= NR) return;
    int b = getb(batch, i, g_is64);
    float v = g_s[i];
    int b0 = __shfl_sync(m, b, 0);
    if (m == 0xFFFFFFFFu && __all_sync(m, b == b0)) {
#pragma unroll
        for (int o = 16; o; o >>= 1)
            v = fmaxf(v, __shfl_xor_sync(0xFFFFFFFFu, v, o));
        if ((threadIdx.x & 31) == 0) atomic_fmax(&g_max[b], v);
    } else {
        atomic_fmax(&g_max[b], v);
    }
}

// ---------------- exp + segment sum (warp-aggregated) ----------------------
__global__ void expsum_kernel(const void* batch) {
    int i = blockIdx.x * blockDim.x + threadIdx.x;
    unsigned m = __ballot_sync(0xFFFFFFFF, i < NR);
    if (i >= NR) return;
    int b = getb(batch, i, g_is64);
    float e = expf(g_s[i] - g_max[b]);
    g_s[i] = e;
    int b0 = __shfl_sync(m, b, 0);
    if (m == 0xFFFFFFFFu && __all_sync(m, b == b0)) {
        float s = e;
#pragma unroll
        for (int o = 16; o; o >>= 1)
            s += __shfl_xor_sync(0xFFFFFFFFu, s, o);
        if ((threadIdx.x & 31) == 0) atomicAdd(&g_sum[b], s);
    } else {
        atomicAdd(&g_sum[b], e);
    }
}

__global__ void recip_kernel() {
    int i = blockIdx.x * blockDim.x + threadIdx.x;
    if (i < BS) g_inv[i] = 1.f / g_sum[i];
}

// ---------------- weighted pooling: exploits sorted batch ------------------
#define RPB 256
__global__ void pool_kernel(const float* __restrict__ x, const void* batch) {
    int start = blockIdx.x * RPB;
    int end = min(start + RPB, NR);
    if (start >= NR) return;
    const int col = threadIdx.x;
    const int is64 = g_is64;
    float acc = 0.f;
    int cur = getb(batch, start, is64);
    for (int r = start; r < end; r++) {
        int b = getb(batch, r, is64);
        if (b != cur) {
            atomicAdd(&g_pooled[(size_t)cur * DD + col], acc);
            acc = 0.f;
            cur = b;
        }
        float alpha = g_s[r] * g_inv[b];
        acc += alpha * x[(size_t)r * DD + col];
    }
    atomicAdd(&g_pooled[(size_t)cur * DD + col], acc);
}

// ---------------- output GEMM: out = pooled @ Wp + bp ----------------------
__global__ void out_kernel(const float* __restrict__ Wp,
                           const float* __restrict__ bp,
                           float* __restrict__ out) {
    __shared__ float Ps[16][256];
    const int row0 = blockIdx.x * 16;
    const int tid = threadIdx.x;
    for (int idx = tid; idx < 16 * 256; idx += 256)
        (&Ps[0][0])[idx] = g_pooled[(size_t)row0 * DD + idx];
    __syncthreads();
    float acc[16];
#pragma unroll
    for (int r = 0; r < 16; r++) acc[r] = 0.f;
    const int col = tid;
    for (int k = 0; k < 256; k++) {
        float w = Wp[(size_t)k * DD + col];
#pragma unroll
        for (int r = 0; r < 16; r++) acc[r] += Ps[r][k] * w;
    }
    const float bb = bp[col];
#pragma unroll
    for (int r = 0; r < 16; r++)
        out[(size_t)(row0 + r) * DD + col] = acc[r] + bb;
}

// ---------------- launch ----------------------------------------------------
extern "C" void kernel_launch(void* const* d_in, const int* in_sizes, int n_in,
                              void* d_out, int out_size) {
    const float* x  = (const float*)d_in[0];
    const void*  bt = d_in[1];
    const float* W1 = (const float*)d_in[2];
    const float* b1 = (const float*)d_in[3];
    const float* w2 = (const float*)d_in[4];
    const float* b2 = (const float*)d_in[5];
    const float* Wp = (const float*)d_in[6];
    const float* bp = (const float*)d_in[7];
    float* out = (float*)d_out;

    cudaFuncSetAttribute(score_mma_kernel,
                         cudaFuncAttributeMaxDynamicSharedMemorySize, SC_SMEM);

    init_kernel<<<(BS * DD + 255) / 256, 256>>>(bt);
    prep_w1_kernel<<<(DD * DD + 255) / 256, 256>>>(W1);
    dummy_kernel<<<1, 32>>>();   // shifts score to 4th launch (ncu window)
    score_mma_kernel<<<(NR + 127) / 128, 512, SC_SMEM>>>(x, b1, w2, b2);
    segmax_kernel<<<(NR + 255) / 256, 256>>>(bt);
    expsum_kernel<<<(NR + 255) / 256, 256>>>(bt);
    recip_kernel<<<(BS + 255) / 256, 256>>>();
    pool_kernel<<<(NR + RPB - 1) / RPB, 256>>>(x, bt);
    out_kernel<<<BS / 16, 256>>>(Wp, bp, out);
}

// round 9
// speedup vs baseline: 9.9478x; 1.7748x over previous
#include <cuda_runtime.h>
#include <cuda_fp16.h>
#include <math.h>
#include <stdint.h>

#define NR 1000000
#define DD 256
#define BS 4096

// ---------------- scratch (device globals: no allocations allowed) ----------
__device__ float g_s[NR];          // raw scores
__device__ float g_pooled[BS * DD];
__device__ int   g_is64;           // batch dtype flag: 1 = int64, 0 = int32
// W1 as fp16, transposed to [n][k] (K contiguous per output column)
__device__ __align__(16) __half g_Bh16[DD * DD];

__device__ __forceinline__ int getb(const void* p, int i, int is64) {
    if (is64) return (int)((const long long*)p)[i];
    return ((const int*)p)[i];
}

__device__ __forceinline__ uint32_t smem_u32(const void* p) {
    uint32_t a;
    asm("{ .reg .u64 t; cvta.to.shared.u64 t, %1; cvt.u32.u64 %0, t; }"
        : "=r"(a) : "l"(p));
    return a;
}
__device__ __forceinline__ void ldm_x4(uint32_t* r, uint32_t addr) {
    asm volatile("ldmatrix.sync.aligned.m8n8.x4.shared.b16 {%0,%1,%2,%3}, [%4];"
        : "=r"(r[0]), "=r"(r[1]), "=r"(r[2]), "=r"(r[3]) : "r"(addr));
}
__device__ __forceinline__ void mma_f16(float* d, const uint32_t* a,
                                        const uint32_t* b) {
    asm volatile(
        "mma.sync.aligned.m16n8k16.row.col.f32.f16.f16.f32 "
        "{%0,%1,%2,%3}, {%4,%5,%6,%7}, {%8,%9}, {%0,%1,%2,%3};"
        : "+f"(d[0]), "+f"(d[1]), "+f"(d[2]), "+f"(d[3])
        : "r"(a[0]), "r"(a[1]), "r"(a[2]), "r"(a[3]), "r"(b[0]), "r"(b[1]));
}
__device__ __forceinline__ void cpasync16(uint32_t dst, const void* src) {
    asm volatile("cp.async.cg.shared.global [%0], [%1], 16;"
                 :: "r"(dst), "l"(src) : "memory");
}
#define CP_COMMIT() asm volatile("cp.async.commit_group;" ::: "memory")
#define CP_WAIT0()  asm volatile("cp.async.wait_group 0;" ::: "memory")

__device__ __forceinline__ float tanh_fast(float v) {
    float e = __expf(2.f * v);
    return 1.f - __fdividef(2.f, e + 1.f);
}

// ---------------- init: detect batch dtype only -----------------------------
__global__ void init_kernel(const void* batch) {
    if (threadIdx.x == 0 && blockIdx.x == 0) {
        long long v = ((const long long*)batch)[NR / 2 - 1];
        g_is64 = (v >= 0 && v < BS) ? 1 : 0;
    }
}

// ---------------- prep: W1 -> fp16, transpose to [n][k] ---------------------
__global__ void prep_w1_kernel(const float* __restrict__ W1) {
    int i = blockIdx.x * blockDim.x + threadIdx.x;
    if (i >= DD * DD) return;
    int k = i >> 8, n = i & 255;                     // W1[k][n]
    g_Bh16[n * DD + k] = __float2half_rn(W1[i]);
}

// ---------------- dummy: keeps score at 4th launch (ncu window) -------------
__global__ void dummy_kernel() {}

// ---------------- score GEMM: single-pass fp16 ------------------------------
// CTA: 512 threads = 16 warps (4 M x 4 N). Tile M=128, N=256, K chunks of 64.
#define APITCH 144
#define BUFSZ  55296
#define OF_A   0
#define OF_B   18432
#define SC_SMEM (2 * BUFSZ)
__global__ __launch_bounds__(512, 1)
void score_mma_kernel(const float* __restrict__ x, const float* __restrict__ b1,
                      const float* __restrict__ w2, const float* __restrict__ b2p) {
    extern __shared__ char smem[];
    const uint32_t sb = smem_u32(smem);
    const int tid = threadIdx.x;
    const int wid = tid >> 5, lane = tid & 31;
    const int mw = wid & 3;          // M warp: rows mw*32 .. +31
    const int nw = wid >> 2;         // N warp: cols nw*64 .. +63
    const int bm = blockIdx.x * 128;

    float acc[2][8][4];
#pragma unroll
    for (int a = 0; a < 2; a++)
#pragma unroll
        for (int b = 0; b < 8; b++)
#pragma unroll
            for (int c = 0; c < 4; c++) acc[a][b][c] = 0.f;

    const int a_row_in = (lane & 15);
    const int a_k_in   = (lane & 16) >> 1;
    const int b_n_in   = (lane & 7) + ((lane & 16) >> 1);
    const int b_k_in   = (lane & 8);

    auto loadB = [&](int c, int buf) {
        uint32_t base = sb + buf * BUFSZ;
#pragma unroll
        for (int t = 0; t < 4; t++) {
            int idx = tid + t * 512;             // 0..2047
            int n = idx >> 3, q = idx & 7;
            uint32_t doff = (uint32_t)n * APITCH + (uint32_t)q * 16;
            size_t gsrc = (size_t)n * DD + c * 64 + q * 8;
            cpasync16(base + OF_B + doff, g_Bh16 + gsrc);
        }
        CP_COMMIT();
    };
    auto loadA = [&](int c, float4* st) {
#pragma unroll
        for (int t = 0; t < 4; t++) {
            int idx = tid + t * 512;             // 0..2047 float4s
            int r = idx >> 4, q = idx & 15;
            int grow = bm + r;
            st[t] = (grow < NR)
                ? *(const float4*)(x + (size_t)grow * DD + c * 64 + q * 4)
                : make_float4(0.f, 0.f, 0.f, 0.f);
        }
    };
    auto storeA = [&](const float4* st, int buf) {
        char* base = smem + buf * BUFSZ;
#pragma unroll
        for (int t = 0; t < 4; t++) {
            int idx = tid + t * 512;
            int r = idx >> 4, q = idx & 15;
            __half2 h0 = __floats2half2_rn(st[t].x, st[t].y);
            __half2 h1 = __floats2half2_rn(st[t].z, st[t].w);
            uint32_t off = (uint32_t)r * APITCH + (uint32_t)q * 8;
            *(uint2*)(base + OF_A + off) =
                make_uint2(*(uint32_t*)&h0, *(uint32_t*)&h1);
        }
    };

    // ---- prologue: fill buffer 0 ----
    float4 st[4];
    loadB(0, 0);
    loadA(0, st);
    storeA(st, 0);
    CP_WAIT0();
    __syncthreads();

#pragma unroll 1
    for (int c = 0; c < 4; c++) {
        const int cur = c & 1, nxt = cur ^ 1;
        if (c < 3) {
            loadB(c + 1, nxt);       // cp.async overlaps MMA burst
            loadA(c + 1, st);        // LDG latency hidden under MMA burst
        }
        // ---- compute on buf[cur]: 4 k16 steps ----
        const uint32_t abase = sb + (uint32_t)cur * BUFSZ;
#pragma unroll
        for (int ks = 0; ks < 4; ks++) {
            const int k0 = ks * 16;
            uint32_t ah[2][4];
#pragma unroll
            for (int mt = 0; mt < 2; mt++) {
                uint32_t row = (uint32_t)(mw * 32 + mt * 16 + a_row_in);
                uint32_t col = (uint32_t)(k0 + a_k_in);
                ldm_x4(ah[mt], abase + OF_A + row * APITCH + col * 2);
            }
#pragma unroll
            for (int p = 0; p < 4; p++) {
                uint32_t nrow = (uint32_t)(nw * 64 + p * 16 + b_n_in);
                uint32_t col = (uint32_t)(k0 + b_k_in);
                uint32_t bh[4];
                ldm_x4(bh, abase + OF_B + nrow * APITCH + col * 2);
#pragma unroll
                for (int mt = 0; mt < 2; mt++) {
#pragma unroll
                    for (int half = 0; half < 2; half++) {
                        mma_f16(acc[mt][p * 2 + half], ah[mt], bh + half * 2);
                    }
                }
            }
        }
        if (c < 3) {
            storeA(st, nxt);         // short convert tail
            CP_WAIT0();              // B(c+1) landed
        }
        __syncthreads();
    }

    // ---- epilogue: s = sum_n w2[n]*tanh(h + b1[n]) + b2 ----
    float part[2][2] = {{0.f, 0.f}, {0.f, 0.f}};
#pragma unroll
    for (int mt = 0; mt < 2; mt++) {
#pragma unroll
        for (int nt = 0; nt < 8; nt++) {
            int col0 = nw * 64 + nt * 8 + (lane & 3) * 2;
            float w0 = __ldg(w2 + col0), w1v = __ldg(w2 + col0 + 1);
            float c0 = __ldg(b1 + col0), c1 = __ldg(b1 + col0 + 1);
            const float* d = acc[mt][nt];
            part[mt][0] += w0 * tanh_fast(d[0] + c0) + w1v * tanh_fast(d[1] + c1);
            part[mt][1] += w0 * tanh_fast(d[2] + c0) + w1v * tanh_fast(d[3] + c1);
        }
    }
#pragma unroll
    for (int mt = 0; mt < 2; mt++)
#pragma unroll
        for (int h = 0; h < 2; h++) {
            part[mt][h] += __shfl_xor_sync(0xFFFFFFFF, part[mt][h], 1);
            part[mt][h] += __shfl_xor_sync(0xFFFFFFFF, part[mt][h], 2);
        }
    __syncthreads();
    float* red = (float*)smem;                    // [128][4]
    if ((lane & 3) == 0) {
#pragma unroll
        for (int mt = 0; mt < 2; mt++)
#pragma unroll
            for (int h = 0; h < 2; h++) {
                int rowl = mw * 32 + mt * 16 + h * 8 + (lane >> 2);
                red[rowl * 4 + nw] = part[mt][h];
            }
    }
    __syncthreads();
    if (tid < 128) {
        int grow = bm + tid;
        if (grow < NR) {
            float v = red[tid * 4] + red[tid * 4 + 1] + red[tid * 4 + 2] +
                      red[tid * 4 + 3];
            g_s[grow] = v + __ldg(b2p);
        }
    }
}

// ---------------- fused segment softmax + pooling (1 block / segment) -------
#define ESCAP 2048
__global__ __launch_bounds__(256)
void pool2_kernel(const float* __restrict__ x, const void* batch) {
    __shared__ float es[ESCAP];
    __shared__ float red[16];
    __shared__ int bounds[2];
    const int seg = blockIdx.x;
    const int tid = threadIdx.x;
    const int is64 = g_is64;

    if (tid < 2) {                                 // binary search bounds
        int target = seg + tid;
        int lo = 0, hi = NR;
        while (lo < hi) {
            int mid = (lo + hi) >> 1;
            if (getb(batch, mid, is64) < target) lo = mid + 1; else hi = mid;
        }
        bounds[tid] = lo;
    }
    __syncthreads();
    const int lo = bounds[0], hi = bounds[1];
    const int cnt = hi - lo;
    if (cnt <= 0) { g_pooled[(size_t)seg * DD + tid] = 0.f; return; }

    // phase 1: segment max
    float m = -INFINITY;
    for (int r = lo + tid; r < hi; r += 256) m = fmaxf(m, g_s[r]);
#pragma unroll
    for (int o = 16; o; o >>= 1) m = fmaxf(m, __shfl_xor_sync(0xFFFFFFFFu, m, o));
    if ((tid & 31) == 0) red[tid >> 5] = m;
    __syncthreads();
    if (tid == 0) {
        float t = red[0];
#pragma unroll
        for (int i = 1; i < 8; i++) t = fmaxf(t, red[i]);
        red[0] = t;
    }
    __syncthreads();
    const float smax = red[0];
    const bool fit = (cnt <= ESCAP);

    // phase 2: exp + sum
    float s = 0.f;
    for (int r = lo + tid; r < hi; r += 256) {
        float e = __expf(g_s[r] - smax);
        if (fit) es[r - lo] = e;
        s += e;
    }
#pragma unroll
    for (int o = 16; o; o >>= 1) s += __shfl_xor_sync(0xFFFFFFFFu, s, o);
    if ((tid & 31) == 0) red[8 + (tid >> 5)] = s;
    __syncthreads();
    if (tid == 0) {
        float t = 0.f;
#pragma unroll
        for (int i = 0; i < 8; i++) t += red[8 + i];
        red[8] = t;
    }
    __syncthreads();
    const float inv = 1.f / red[8];

    // phase 3: acc = sum_r e_r * x[r][col]; pooled = acc * inv
    float a0 = 0.f, a1 = 0.f, a2 = 0.f, a3 = 0.f;
    const float* xp = x + (size_t)lo * DD + tid;
    if (fit) {
        int r = 0;
        for (; r + 4 <= cnt; r += 4) {
            a0 += es[r]     * xp[(size_t)r * DD];
            a1 += es[r + 1] * xp[(size_t)(r + 1) * DD];
            a2 += es[r + 2] * xp[(size_t)(r + 2) * DD];
            a3 += es[r + 3] * xp[(size_t)(r + 3) * DD];
        }
        for (; r < cnt; r++) a0 += es[r] * xp[(size_t)r * DD];
    } else {
        for (int r = 0; r < cnt; r++)
            a0 += __expf(g_s[lo + r] - smax) * xp[(size_t)r * DD];
    }
    g_pooled[(size_t)seg * DD + tid] = (a0 + a1 + a2 + a3) * inv;
}

// ---------------- output GEMM: out = pooled @ Wp + bp ----------------------
__global__ void out_kernel(const float* __restrict__ Wp,
                           const float* __restrict__ bp,
                           float* __restrict__ out) {
    __shared__ float Ps[16][256];
    const int row0 = blockIdx.x * 16;
    const int tid = threadIdx.x;
    for (int idx = tid; idx < 16 * 256; idx += 256)
        (&Ps[0][0])[idx] = g_pooled[(size_t)row0 * DD + idx];
    __syncthreads();
    float acc[16];
#pragma unroll
    for (int r = 0; r < 16; r++) acc[r] = 0.f;
    const int col = tid;
    for (int k = 0; k < 256; k++) {
        float w = Wp[(size_t)k * DD + col];
#pragma unroll
        for (int r = 0; r < 16; r++) acc[r] += Ps[r][k] * w;
    }
    const float bb = bp[col];
#pragma unroll
    for (int r = 0; r < 16; r++)
        out[(size_t)(row0 + r) * DD + col] = acc[r] + bb;
}

// ---------------- launch ----------------------------------------------------
extern "C" void kernel_launch(void* const* d_in, const int* in_sizes, int n_in,
                              void* d_out, int out_size) {
    const float* x  = (const float*)d_in[0];
    const void*  bt = d_in[1];
    const float* W1 = (const float*)d_in[2];
    const float* b1 = (const float*)d_in[3];
    const float* w2 = (const float*)d_in[4];
    const float* b2 = (const float*)d_in[5];
    const float* Wp = (const float*)d_in[6];
    const float* bp = (const float*)d_in[7];
    float* out = (float*)d_out;

    cudaFuncSetAttribute(score_mma_kernel,
                         cudaFuncAttributeMaxDynamicSharedMemorySize, SC_SMEM);

    init_kernel<<<1, 32>>>(bt);
    prep_w1_kernel<<<(DD * DD + 255) / 256, 256>>>(W1);
    dummy_kernel<<<1, 32>>>();   // keeps score at 4th launch (ncu window)
    score_mma_kernel<<<(NR + 127) / 128, 512, SC_SMEM>>>(x, b1, w2, b2);
    pool2_kernel<<<BS, 256>>>(x, bt);
    out_kernel<<<BS / 16, 256>>>(Wp, bp, out);
}

// round 10
// speedup vs baseline: 10.5424x; 1.0598x over previous
#include <cuda_runtime.h>
#include <cuda_fp16.h>
#include <math.h>
#include <stdint.h>

#define NR 1000000
#define DD 256
#define BS 4096

// ---------------- scratch (device globals: no allocations allowed) ----------
__device__ float g_s[NR];          // raw scores
__device__ float g_pooled[BS * DD];
__device__ int   g_is64;           // batch dtype flag: 1 = int64, 0 = int32
// W1 as fp16, transposed to [n][k] (K contiguous per output column)
__device__ __align__(16) __half g_Bh16[DD * DD];

__device__ __forceinline__ int getb(const void* p, int i, int is64) {
    if (is64) return (int)((const long long*)p)[i];
    return ((const int*)p)[i];
}

__device__ __forceinline__ uint32_t smem_u32(const void* p) {
    uint32_t a;
    asm("{ .reg .u64 t; cvta.to.shared.u64 t, %1; cvt.u32.u64 %0, t; }"
        : "=r"(a) : "l"(p));
    return a;
}
__device__ __forceinline__ void ldm_x4(uint32_t* r, uint32_t addr) {
    asm volatile("ldmatrix.sync.aligned.m8n8.x4.shared.b16 {%0,%1,%2,%3}, [%4];"
        : "=r"(r[0]), "=r"(r[1]), "=r"(r[2]), "=r"(r[3]) : "r"(addr));
}
__device__ __forceinline__ void mma_f16(float* d, const uint32_t* a,
                                        const uint32_t* b) {
    asm volatile(
        "mma.sync.aligned.m16n8k16.row.col.f32.f16.f16.f32 "
        "{%0,%1,%2,%3}, {%4,%5,%6,%7}, {%8,%9}, {%0,%1,%2,%3};"
        : "+f"(d[0]), "+f"(d[1]), "+f"(d[2]), "+f"(d[3])
        : "r"(a[0]), "r"(a[1]), "r"(a[2]), "r"(a[3]), "r"(b[0]), "r"(b[1]));
}
__device__ __forceinline__ void cpasync16(uint32_t dst, const void* src) {
    asm volatile("cp.async.cg.shared.global [%0], [%1], 16;"
                 :: "r"(dst), "l"(src) : "memory");
}
#define CP_COMMIT() asm volatile("cp.async.commit_group;" ::: "memory")
#define CP_WAIT0()  asm volatile("cp.async.wait_group 0;" ::: "memory")

__device__ __forceinline__ float tanh_fast(float v) {
    float e = __expf(2.f * v);
    return 1.f - __fdividef(2.f, e + 1.f);
}

// ---------------- init: detect batch dtype only -----------------------------
__global__ void init_kernel(const void* batch) {
    if (threadIdx.x == 0 && blockIdx.x == 0) {
        long long v = ((const long long*)batch)[NR / 2 - 1];
        g_is64 = (v >= 0 && v < BS) ? 1 : 0;
    }
}

// ---------------- prep: W1 -> fp16, transpose to [n][k] ---------------------
__global__ void prep_w1_kernel(const float* __restrict__ W1) {
    int i = blockIdx.x * blockDim.x + threadIdx.x;
    if (i >= DD * DD) return;
    int k = i >> 8, n = i & 255;                     // W1[k][n]
    g_Bh16[n * DD + k] = __float2half_rn(W1[i]);
}

// ---------------- dummy: keeps score at 4th launch (ncu window) -------------
__global__ void dummy_kernel() {}

// ---------------- score GEMM: single-pass fp16, 2 CTAs/SM -------------------
// CTA: 256 threads = 8 warps (2 M x 4 N). Tile M=64, N=256, K chunks of 64.
// NR = 64 * 15625 exactly -> no bounds checks anywhere.
#define APITCH 144
#define BUFSZ  46080
#define OF_A   0
#define OF_B   9216
#define SC_SMEM (2 * BUFSZ)
__global__ __launch_bounds__(256, 2)
void score_mma_kernel(const float* __restrict__ x, const float* __restrict__ b1,
                      const float* __restrict__ w2, const float* __restrict__ b2p) {
    extern __shared__ char smem[];
    const uint32_t sb = smem_u32(smem);
    const int tid = threadIdx.x;
    const int wid = tid >> 5, lane = tid & 31;
    const int mw = wid & 1;          // M warp: rows mw*32 .. +31
    const int nw = wid >> 1;         // N warp: cols nw*64 .. +63
    const int bm = blockIdx.x * 64;

    float acc[2][8][4];
#pragma unroll
    for (int a = 0; a < 2; a++)
#pragma unroll
        for (int b = 0; b < 8; b++)
#pragma unroll
            for (int c = 0; c < 4; c++) acc[a][b][c] = 0.f;

    const int a_row_in = (lane & 15);
    const int a_k_in   = (lane & 16) >> 1;
    const int b_n_in   = (lane & 7) + ((lane & 16) >> 1);
    const int b_k_in   = (lane & 8);

    auto loadB = [&](int c, int buf) {
        uint32_t base = sb + buf * BUFSZ;
#pragma unroll
        for (int t = 0; t < 8; t++) {
            int idx = tid + t * 256;             // 0..2047
            int n = idx >> 3, q = idx & 7;
            uint32_t doff = (uint32_t)n * APITCH + (uint32_t)q * 16;
            size_t gsrc = (size_t)n * DD + c * 64 + q * 8;
            cpasync16(base + OF_B + doff, g_Bh16 + gsrc);
        }
        CP_COMMIT();
    };
    auto loadA = [&](int c, float4* st) {
#pragma unroll
        for (int t = 0; t < 4; t++) {
            int idx = tid + t * 256;             // 0..1023 float4s
            int r = idx >> 4, q = idx & 15;
            st[t] = *(const float4*)(x + (size_t)(bm + r) * DD + c * 64 + q * 4);
        }
    };
    auto storeA = [&](const float4* st, int buf) {
        char* base = smem + buf * BUFSZ;
#pragma unroll
        for (int t = 0; t < 4; t++) {
            int idx = tid + t * 256;
            int r = idx >> 4, q = idx & 15;
            __half2 h0 = __floats2half2_rn(st[t].x, st[t].y);
            __half2 h1 = __floats2half2_rn(st[t].z, st[t].w);
            uint32_t off = (uint32_t)r * APITCH + (uint32_t)q * 8;
            *(uint2*)(base + OF_A + off) =
                make_uint2(*(uint32_t*)&h0, *(uint32_t*)&h1);
        }
    };

    // ---- prologue: fill buffer 0 ----
    float4 st[4];
    loadB(0, 0);
    loadA(0, st);
    storeA(st, 0);
    CP_WAIT0();
    __syncthreads();

#pragma unroll 1
    for (int c = 0; c < 4; c++) {
        const int cur = c & 1, nxt = cur ^ 1;
        if (c < 3) {
            loadB(c + 1, nxt);       // cp.async overlaps MMA burst
            loadA(c + 1, st);        // LDG latency hidden under MMA burst
        }
        // ---- compute on buf[cur]: 4 k16 steps ----
        const uint32_t abase = sb + (uint32_t)cur * BUFSZ;
#pragma unroll
        for (int ks = 0; ks < 4; ks++) {
            const int k0 = ks * 16;
            uint32_t ah[2][4];
#pragma unroll
            for (int mt = 0; mt < 2; mt++) {
                uint32_t row = (uint32_t)(mw * 32 + mt * 16 + a_row_in);
                uint32_t col = (uint32_t)(k0 + a_k_in);
                ldm_x4(ah[mt], abase + OF_A + row * APITCH + col * 2);
            }
#pragma unroll
            for (int p = 0; p < 4; p++) {
                uint32_t nrow = (uint32_t)(nw * 64 + p * 16 + b_n_in);
                uint32_t col = (uint32_t)(k0 + b_k_in);
                uint32_t bh[4];
                ldm_x4(bh, abase + OF_B + nrow * APITCH + col * 2);
#pragma unroll
                for (int mt = 0; mt < 2; mt++) {
#pragma unroll
                    for (int half = 0; half < 2; half++) {
                        mma_f16(acc[mt][p * 2 + half], ah[mt], bh + half * 2);
                    }
                }
            }
        }
        if (c < 3) {
            storeA(st, nxt);         // short convert tail
            CP_WAIT0();              // B(c+1) landed
        }
        __syncthreads();
    }

    // ---- epilogue: s = sum_n w2[n]*tanh(h + b1[n]) + b2 ----
    float part[2][2] = {{0.f, 0.f}, {0.f, 0.f}};
#pragma unroll
    for (int mt = 0; mt < 2; mt++) {
#pragma unroll
        for (int nt = 0; nt < 8; nt++) {
            int col0 = nw * 64 + nt * 8 + (lane & 3) * 2;
            float w0 = __ldg(w2 + col0), w1v = __ldg(w2 + col0 + 1);
            float c0 = __ldg(b1 + col0), c1 = __ldg(b1 + col0 + 1);
            const float* d = acc[mt][nt];
            part[mt][0] += w0 * tanh_fast(d[0] + c0) + w1v * tanh_fast(d[1] + c1);
            part[mt][1] += w0 * tanh_fast(d[2] + c0) + w1v * tanh_fast(d[3] + c1);
        }
    }
#pragma unroll
    for (int mt = 0; mt < 2; mt++)
#pragma unroll
        for (int h = 0; h < 2; h++) {
            part[mt][h] += __shfl_xor_sync(0xFFFFFFFF, part[mt][h], 1);
            part[mt][h] += __shfl_xor_sync(0xFFFFFFFF, part[mt][h], 2);
        }
    __syncthreads();
    float* red = (float*)smem;                    // [64][4]
    if ((lane & 3) == 0) {
#pragma unroll
        for (int mt = 0; mt < 2; mt++)
#pragma unroll
            for (int h = 0; h < 2; h++) {
                int rowl = mw * 32 + mt * 16 + h * 8 + (lane >> 2);
                red[rowl * 4 + nw] = part[mt][h];
            }
    }
    __syncthreads();
    if (tid < 64) {
        float v = red[tid * 4] + red[tid * 4 + 1] + red[tid * 4 + 2] +
                  red[tid * 4 + 3];
        g_s[bm + tid] = v + __ldg(b2p);
    }
}

// ---------------- fused segment softmax + pooling (1 block / segment) -------
#define ESCAP 2048
__global__ __launch_bounds__(256)
void pool2_kernel(const float* __restrict__ x, const void* batch) {
    __shared__ float es[ESCAP];
    __shared__ float red[16];
    __shared__ int bounds[2];
    const int seg = blockIdx.x;
    const int tid = threadIdx.x;
    const int is64 = g_is64;

    if (tid < 2) {                                 // binary search bounds
        int target = seg + tid;
        int lo = 0, hi = NR;
        while (lo < hi) {
            int mid = (lo + hi) >> 1;
            if (getb(batch, mid, is64) < target) lo = mid + 1; else hi = mid;
        }
        bounds[tid] = lo;
    }
    __syncthreads();
    const int lo = bounds[0], hi = bounds[1];
    const int cnt = hi - lo;
    if (cnt <= 0) { g_pooled[(size_t)seg * DD + tid] = 0.f; return; }

    // phase 1: segment max
    float m = -INFINITY;
    for (int r = lo + tid; r < hi; r += 256) m = fmaxf(m, g_s[r]);
#pragma unroll
    for (int o = 16; o; o >>= 1) m = fmaxf(m, __shfl_xor_sync(0xFFFFFFFFu, m, o));
    if ((tid & 31) == 0) red[tid >> 5] = m;
    __syncthreads();
    if (tid == 0) {
        float t = red[0];
#pragma unroll
        for (int i = 1; i < 8; i++) t = fmaxf(t, red[i]);
        red[0] = t;
    }
    __syncthreads();
    const float smax = red[0];
    const bool fit = (cnt <= ESCAP);

    // phase 2: exp + sum
    float s = 0.f;
    for (int r = lo + tid; r < hi; r += 256) {
        float e = __expf(g_s[r] - smax);
        if (fit) es[r - lo] = e;
        s += e;
    }
#pragma unroll
    for (int o = 16; o; o >>= 1) s += __shfl_xor_sync(0xFFFFFFFFu, s, o);
    if ((tid & 31) == 0) red[8 + (tid >> 5)] = s;
    __syncthreads();
    if (tid == 0) {
        float t = 0.f;
#pragma unroll
        for (int i = 0; i < 8; i++) t += red[8 + i];
        red[8] = t;
    }
    __syncthreads();
    const float inv = 1.f / red[8];

    // phase 3: acc = sum_r e_r * x[r][col]; pooled = acc * inv
    float a0 = 0.f, a1 = 0.f, a2 = 0.f, a3 = 0.f;
    const float* xp = x + (size_t)lo * DD + tid;
    if (fit) {
        int r = 0;
        for (; r + 4 <= cnt; r += 4) {
            a0 += es[r]     * xp[(size_t)r * DD];
            a1 += es[r + 1] * xp[(size_t)(r + 1) * DD];
            a2 += es[r + 2] * xp[(size_t)(r + 2) * DD];
            a3 += es[r + 3] * xp[(size_t)(r + 3) * DD];
        }
        for (; r < cnt; r++) a0 += es[r] * xp[(size_t)r * DD];
    } else {
        for (int r = 0; r < cnt; r++)
            a0 += __expf(g_s[lo + r] - smax) * xp[(size_t)r * DD];
    }
    g_pooled[(size_t)seg * DD + tid] = (a0 + a1 + a2 + a3) * inv;
}

// ---------------- output GEMM: out = pooled @ Wp + bp ----------------------
__global__ void out_kernel(const float* __restrict__ Wp,
                           const float* __restrict__ bp,
                           float* __restrict__ out) {
    __shared__ float Ps[16][256];
    const int row0 = blockIdx.x * 16;
    const int tid = threadIdx.x;
    for (int idx = tid; idx < 16 * 256; idx += 256)
        (&Ps[0][0])[idx] = g_pooled[(size_t)row0 * DD + idx];
    __syncthreads();
    float acc[16];
#pragma unroll
    for (int r = 0; r < 16; r++) acc[r] = 0.f;
    const int col = tid;
    for (int k = 0; k < 256; k++) {
        float w = Wp[(size_t)k * DD + col];
#pragma unroll
        for (int r = 0; r < 16; r++) acc[r] += Ps[r][k] * w;
    }
    const float bb = bp[col];
#pragma unroll
    for (int r = 0; r < 16; r++)
        out[(size_t)(row0 + r) * DD + col] = acc[r] + bb;
}

// ---------------- launch ----------------------------------------------------
extern "C" void kernel_launch(void* const* d_in, const int* in_sizes, int n_in,
                              void* d_out, int out_size) {
    const float* x  = (const float*)d_in[0];
    const void*  bt = d_in[1];
    const float* W1 = (const float*)d_in[2];
    const float* b1 = (const float*)d_in[3];
    const float* w2 = (const float*)d_in[4];
    const float* b2 = (const float*)d_in[5];
    const float* Wp = (const float*)d_in[6];
    const float* bp = (const float*)d_in[7];
    float* out = (float*)d_out;

    cudaFuncSetAttribute(score_mma_kernel,
                         cudaFuncAttributeMaxDynamicSharedMemorySize, SC_SMEM);

    init_kernel<<<1, 32>>>(bt);
    prep_w1_kernel<<<(DD * DD + 255) / 256, 256>>>(W1);
    dummy_kernel<<<1, 32>>>();   // keeps score at 4th launch (ncu window)
    score_mma_kernel<<<NR / 64, 256, SC_SMEM>>>(x, b1, w2, b2);
    pool2_kernel<<<BS, 256>>>(x, bt);
    out_kernel<<<BS / 16, 256>>>(Wp, bp, out);
}